// round 15
// baseline (speedup 1.0000x reference)
#include <cuda_runtime.h>
#include <cuda_fp16.h>
#include <math.h>
#include <stdint.h>

#define BB  2
#define TT  2048
#define DD  2048
#define HH  16
#define DHH 128
#define MM  (BB*TT)    // 4096
#define NN  (HH*DHH)   // 2048
#define KK  DD         // 2048
#define K2  (KK/2)     // 1024

// Scratch (allocation-free rule: __device__ globals). All fp16x2-packed u32.
// x, o, and weights use PERMUTED k2-groups: within each group of 8 k2-words,
// position p holds k2 q where p = (q<4) ? 2q : 2(q-4)+1  (i.e. order 0,4,1,5,2,6,3,7).
// Weights are n-major: [n][K2]. q/k/v stay plain (attention consumes them).
__device__ uint32_t g_q[(size_t)BB*HH*TT*(DHH/2)];
__device__ uint32_t g_k[(size_t)BB*HH*TT*(DHH/2)];
__device__ uint32_t g_v[(size_t)BB*HH*TT*(DHH/2)];
__device__ uint32_t g_o[(size_t)MM*(NN/2)];      // permuted groups
__device__ uint32_t g_x[(size_t)MM*K2];          // permuted groups
__device__ uint32_t g_wq[(size_t)NN*K2];         // n-major, permuted groups
__device__ uint32_t g_wk[(size_t)NN*K2];
__device__ uint32_t g_wv[(size_t)NN*K2];
__device__ uint32_t g_wp[(size_t)NN*K2];

__device__ __forceinline__ uint32_t f2h2(float a, float b) {
    __half2 h = __floats2half2_rn(a, b);
    return *(uint32_t*)&h;
}
__device__ __forceinline__ float2 h22f2(uint32_t w) {
    return __half22float2(*(__half2*)&w);
}

#define MMA_F16(c, a, b)                                                      \
    asm volatile(                                                             \
        "mma.sync.aligned.m16n8k16.row.col.f32.f16.f16.f32 "                  \
        "{%0,%1,%2,%3}, {%4,%5,%6,%7}, {%8,%9}, {%0,%1,%2,%3};"               \
        : "+f"((c)[0]), "+f"((c)[1]), "+f"((c)[2]), "+f"((c)[3])              \
        : "r"((a)[0]), "r"((a)[1]), "r"((a)[2]), "r"((a)[3]),                 \
          "r"((b)[0]), "r"((b)[1]))

#define LDMATRIX_X4_TRANS(r0, r1, r2, r3, addr)                               \
    asm volatile(                                                             \
        "ldmatrix.sync.aligned.m8n8.x4.trans.shared.b16 {%0,%1,%2,%3}, [%4];" \
        : "=r"(r0), "=r"(r1), "=r"(r2), "=r"(r3) : "r"(addr))

__device__ __forceinline__ uint32_t smem_u32(const void* p) {
    return (uint32_t)__cvta_generic_to_shared(p);
}
#define CP_ASYNC16(dst_u32, src)                                              \
    asm volatile("cp.async.cg.shared.global [%0], [%1], 16;"                  \
                 :: "r"(dst_u32), "l"(src))
#define CP_COMMIT() asm volatile("cp.async.commit_group;")
#define CP_WAIT(n)  asm volatile("cp.async.wait_group %0;" :: "n"(n))

// ---------------------------------------------------------------------------
// Pre-pass 1: pack x fp32 -> fp16x2, permuted k2-groups. One thread per group.
// ---------------------------------------------------------------------------
__global__ __launch_bounds__(256) void pack_x_perm(
    const float* __restrict__ src, uint32_t* __restrict__ dst, int ngroups)
{
    const int i = blockIdx.x * 256 + threadIdx.x;
    if (i >= ngroups) return;
    const int row = i >> 7, grp = i & 127;
    const float* s = src + (size_t)row * KK + grp * 16;
    float f[16];
    #pragma unroll
    for (int j = 0; j < 4; j++) {
        float4 v = ((const float4*)s)[j];
        f[4 * j] = v.x; f[4 * j + 1] = v.y; f[4 * j + 2] = v.z; f[4 * j + 3] = v.w;
    }
    uint32_t o[8];
    #pragma unroll
    for (int p = 0; p < 8; p++) {
        const int q = (p & 1) ? (p >> 1) + 4 : (p >> 1);
        o[p] = f2h2(f[2 * q], f[2 * q + 1]);
    }
    uint32_t* d = dst + (size_t)row * K2 + grp * 8;
    ((uint4*)d)[0] = make_uint4(o[0], o[1], o[2], o[3]);
    ((uint4*)d)[1] = make_uint4(o[4], o[5], o[6], o[7]);
}

// ---------------------------------------------------------------------------
// Pre-pass 2: transpose + pack weights to n-major [n][K2], permuted groups.
// 32k x 32n smem tile.
// ---------------------------------------------------------------------------
__device__ __forceinline__ void pack_tile_perm(
    const float* __restrict__ src, uint32_t* __restrict__ dst,
    int ld, int k0, int n0, int tid)
{
    __shared__ float t[32][33];
    const int tx = tid & 31, ty = tid >> 5;
    #pragma unroll
    for (int i = 0; i < 32; i += 8)
        t[ty + i][tx] = src[(size_t)(k0 + ty + i) * ld + n0 + tx];
    __syncthreads();
    const int r = tid >> 3;          // n within tile
    const int c = (tid & 7) * 2;     // local q base (q = local k2, 0..15)
    #pragma unroll
    for (int e = 0; e < 2; e++) {
        const int q = c + e;
        const int pp = (q & 4) ? ((q & 3) * 2 + 1) : ((q & 3) * 2);
        const int outk2 = (k0 >> 1) + (q >> 3) * 8 + pp;
        dst[(size_t)(n0 + r) * K2 + outk2] = f2h2(t[2 * q][r], t[2 * q + 1][r]);
    }
}

__global__ __launch_bounds__(256) void pack_w_qkv(
    const float* __restrict__ Wq, const float* __restrict__ Wk,
    const float* __restrict__ Wv,
    uint32_t* __restrict__ dq, uint32_t* __restrict__ dk,
    uint32_t* __restrict__ dv)
{
    const int z = blockIdx.z, which = z >> 4, h = z & 15;
    const float* src = ((which == 0) ? Wq : (which == 1) ? Wk : Wv)
                       + (size_t)h * KK * 128;
    uint32_t* dst = ((which == 0) ? dq : (which == 1) ? dk : dv)
                    + (size_t)h * 128 * K2;
    pack_tile_perm(src, dst, 128, blockIdx.x * 32, blockIdx.y * 32, threadIdx.x);
}

__global__ __launch_bounds__(256) void pack_w_p(
    const float* __restrict__ W, uint32_t* __restrict__ dst)
{
    pack_tile_perm(W, dst, NN, blockIdx.x * 32, blockIdx.y * 32, threadIdx.x);
}

// GEMM geometry: BM=BN=128, K-chunk=16 (8 u32), 3 stages, 8 warps 2x4, wt 64x32.
// Both operand stages are [128 rows][8 u32] permuted-group layout -> LDS.64 frags.
#define LDG 8
#define STG (128 * LDG)                    // 1024 u32 per stage per operand
#define GEMM_SMEM (6 * STG * 4)            // 24576 bytes

// ---------------------------------------------------------------------------
// Fused QKV fp16 GEMM. A [M][K2] permuted; W per-head [n][K2] permuted.
// Output packed fp16 plain layout [B,H,T,Dh/2] (consumed by attention).
// ---------------------------------------------------------------------------
__global__ __launch_bounds__(256, 2) void gemm_qkv(
    const uint32_t* __restrict__ A,
    const uint32_t* __restrict__ Wq, const float* __restrict__ bq,
    const uint32_t* __restrict__ Wk, const float* __restrict__ bk,
    const uint32_t* __restrict__ Wv, const float* __restrict__ bv,
    uint32_t* __restrict__ Cq, uint32_t* __restrict__ Ck, uint32_t* __restrict__ Cv)
{
    extern __shared__ uint32_t smu[];
    uint32_t* As = smu;                 // [3][128][8]
    uint32_t* Bs = smu + 3 * STG;       // [3][128][8]

    const int bx = blockIdx.x, by = blockIdx.y, bz = blockIdx.z;
    const int tid = threadIdx.x;
    const int wid = tid >> 5, lane = tid & 31;
    const int gid = lane >> 2, tig = lane & 3;
    const int wr = wid >> 2, wc = wid & 3;
    const int m0 = by * 128;

    const uint32_t* W  = (bz == 0) ? Wq : (bz == 1) ? Wk : Wv;
    const float* bias  = (bz == 0) ? bq : (bz == 1) ? bk : bv;
    uint32_t* C        = (bz == 0) ? Cq : (bz == 1) ? Ck : Cv;

    const int srow = tid >> 1, skoff = (tid & 1) * 4;
    const uint32_t* Asrc = A + (size_t)(m0 + srow) * K2 + skoff;
    const uint32_t* Bsrc = W + (size_t)(bx * 128 + srow) * K2 + skoff;
    const uint32_t soff = (srow * LDG + skoff) * 4;   // byte offset in stage

    auto load_stage = [&](int s, int k2b) {
        CP_ASYNC16(smem_u32(As) + s * STG * 4 + soff, Asrc + k2b);
        CP_ASYNC16(smem_u32(Bs) + s * STG * 4 + soff, Bsrc + k2b);
    };

    float acc[4][4][4];
    #pragma unroll
    for (int i = 0; i < 4; i++)
        #pragma unroll
        for (int j = 0; j < 4; j++)
            #pragma unroll
            for (int e = 0; e < 4; e++) acc[i][j][e] = 0.f;

    load_stage(0, 0); CP_COMMIT();
    load_stage(1, 8); CP_COMMIT();

    int cur = 0, nxt = 2, knext = 16;
    for (int it = 0; it < 128; it++) {
        CP_WAIT(1);
        __syncthreads();

        const uint32_t* Ac = As + cur * STG;
        const uint32_t* Bc = Bs + cur * STG;

        uint32_t af[4][4], bf[4][2];
        #pragma unroll
        for (int ma = 0; ma < 4; ma++) {
            const uint32_t* p0 = Ac + (wr * 64 + ma * 16 + gid) * LDG + 2 * tig;
            uint2 lo = *(const uint2*)p0;
            uint2 hi = *(const uint2*)(p0 + 8 * LDG);
            af[ma][0] = lo.x; af[ma][2] = lo.y;
            af[ma][1] = hi.x; af[ma][3] = hi.y;
        }
        #pragma unroll
        for (int na = 0; na < 4; na++) {
            uint2 b = *(const uint2*)(Bc + (wc * 32 + na * 8 + gid) * LDG + 2 * tig);
            bf[na][0] = b.x; bf[na][1] = b.y;
        }
        #pragma unroll
        for (int ma = 0; ma < 4; ma++)
            #pragma unroll
            for (int na = 0; na < 4; na++)
                MMA_F16(acc[ma][na], af[ma], bf[na]);

        if (knext < K2) load_stage(nxt, knext);
        CP_COMMIT();
        knext += 8;
        cur = (cur == 2) ? 0 : cur + 1;
        nxt = (nxt == 2) ? 0 : nxt + 1;
    }

    // Epilogue: bias + pack fp16, plain headed layout [B,H,T,Dh/2]
    #pragma unroll
    for (int ma = 0; ma < 4; ma++) {
        #pragma unroll
        for (int na = 0; na < 4; na++) {
            const int r   = m0 + wr * 64 + ma * 16 + gid;
            const int nl  = wc * 32 + na * 8 + 2 * tig;
            const int ng  = bx * 128 + nl;
            const float b0 = bias[ng], b1 = bias[ng + 1];
            const int col2 = nl >> 1;
            const int bb0 = r >> 11,       t0 = r & (TT - 1);
            const int bb1 = (r + 8) >> 11, t1 = (r + 8) & (TT - 1);
            C[(((size_t)(bb0 * HH + bx)) * TT + t0) * 64 + col2] =
                f2h2(acc[ma][na][0] + b0, acc[ma][na][1] + b1);
            C[(((size_t)(bb1 * HH + bx)) * TT + t1) * 64 + col2] =
                f2h2(acc[ma][na][2] + b0, acc[ma][na][3] + b1);
        }
    }
}

// ---------------------------------------------------------------------------
// Output-projection fp16 GEMM: A = o (permuted), B = wp [n][K2] permuted.
// ---------------------------------------------------------------------------
__global__ __launch_bounds__(256, 2) void gemm_proj(
    const uint32_t* __restrict__ A, const uint32_t* __restrict__ W,
    const float* __restrict__ bias, float* __restrict__ C)
{
    extern __shared__ uint32_t smu[];
    uint32_t* As = smu;
    uint32_t* Bs = smu + 3 * STG;

    const int bx = blockIdx.x, by = blockIdx.y, tid = threadIdx.x;
    const int wid = tid >> 5, lane = tid & 31;
    const int gid = lane >> 2, tig = lane & 3;
    const int wr = wid >> 2, wc = wid & 3;
    const int m0 = by * 128;

    const int srow = tid >> 1, skoff = (tid & 1) * 4;
    const uint32_t* Asrc = A + (size_t)(m0 + srow) * K2 + skoff;
    const uint32_t* Bsrc = W + (size_t)(bx * 128 + srow) * K2 + skoff;
    const uint32_t soff = (srow * LDG + skoff) * 4;

    auto load_stage = [&](int s, int k2b) {
        CP_ASYNC16(smem_u32(As) + s * STG * 4 + soff, Asrc + k2b);
        CP_ASYNC16(smem_u32(Bs) + s * STG * 4 + soff, Bsrc + k2b);
    };

    float acc[4][4][4];
    #pragma unroll
    for (int i = 0; i < 4; i++)
        #pragma unroll
        for (int j = 0; j < 4; j++)
            #pragma unroll
            for (int e = 0; e < 4; e++) acc[i][j][e] = 0.f;

    load_stage(0, 0); CP_COMMIT();
    load_stage(1, 8); CP_COMMIT();

    int cur = 0, nxt = 2, knext = 16;
    for (int it = 0; it < 128; it++) {
        CP_WAIT(1);
        __syncthreads();

        const uint32_t* Ac = As + cur * STG;
        const uint32_t* Bc = Bs + cur * STG;

        uint32_t af[4][4], bf[4][2];
        #pragma unroll
        for (int ma = 0; ma < 4; ma++) {
            const uint32_t* p0 = Ac + (wr * 64 + ma * 16 + gid) * LDG + 2 * tig;
            uint2 lo = *(const uint2*)p0;
            uint2 hi = *(const uint2*)(p0 + 8 * LDG);
            af[ma][0] = lo.x; af[ma][2] = lo.y;
            af[ma][1] = hi.x; af[ma][3] = hi.y;
        }
        #pragma unroll
        for (int na = 0; na < 4; na++) {
            uint2 b = *(const uint2*)(Bc + (wc * 32 + na * 8 + gid) * LDG + 2 * tig);
            bf[na][0] = b.x; bf[na][1] = b.y;
        }
        #pragma unroll
        for (int ma = 0; ma < 4; ma++)
            #pragma unroll
            for (int na = 0; na < 4; na++)
                MMA_F16(acc[ma][na], af[ma], bf[na]);

        if (knext < K2) load_stage(nxt, knext);
        CP_COMMIT();
        knext += 8;
        cur = (cur == 2) ? 0 : cur + 1;
        nxt = (nxt == 2) ? 0 : nxt + 1;
    }

    #pragma unroll
    for (int ma = 0; ma < 4; ma++) {
        #pragma unroll
        for (int na = 0; na < 4; na++) {
            const int r  = m0 + wr * 64 + ma * 16 + gid;
            const int nl = wc * 32 + na * 8 + 2 * tig;
            const int ng = bx * 128 + nl;
            const float b0 = bias[ng], b1 = bias[ng + 1];
            float2 v0, v1;
            v0.x = acc[ma][na][0] + b0; v0.y = acc[ma][na][1] + b1;
            v1.x = acc[ma][na][2] + b0; v1.y = acc[ma][na][3] + b1;
            *(float2*)(C + (size_t)r * NN + ng) = v0;
            *(float2*)(C + (size_t)(r + 8) * NN + ng) = v1;
        }
    }
}

// ---------------------------------------------------------------------------
// Causal flash attention (R14 config): Br=128, Bc=64, 8 warps, big-first,
// P in registers, 3-buffer K/V ring. Epilogue writes o in PERMUTED group
// order for the proj GEMM (same values, permuted positions).
// ---------------------------------------------------------------------------
#define LDKV 68
#define KVBUF (64 * LDKV)
#define ATTN_SMEM (6 * KVBUF * 4)     // 104448 bytes

__global__ __launch_bounds__(256) void attn_f16(
    const uint32_t* __restrict__ Q, const uint32_t* __restrict__ Kg,
    const uint32_t* __restrict__ Vg, uint32_t* __restrict__ O)
{
    extern __shared__ uint32_t shu[];
    uint32_t* sK = shu;                // [3][64][68]; Q staging [128][68]
    uint32_t* sV = shu + 3 * KVBUF;    // [3][64][68]

    const int bh = blockIdx.y;
    const int q0 = (int)(gridDim.x - 1 - blockIdx.x) * 128;   // big-first
    const int tid = threadIdx.x, wid = tid >> 5, lane = tid & 31;
    const int gid = lane >> 2, tig = lane & 3;
    const int wrow = wid * 16;
    const float scale = 0.08838834764831845f;   // 1/sqrt(128)

    const uint32_t* Qb = Q  + (size_t)bh * TT * 64;
    const uint32_t* Kb = Kg + (size_t)bh * TT * 64;
    const uint32_t* Vb = Vg + (size_t)bh * TT * 64;

    // ---- Stage Q (scale + fp16 re-round) into sK region ----
    #pragma unroll
    for (int ch = 0; ch < 8; ch++) {
        const int i = tid + ch * 256;
        const int r = i >> 4, c4 = (i & 15) * 4;
        uint4 w = *(const uint4*)(Qb + (size_t)(q0 + r) * 64 + c4);
        float2 f0 = h22f2(w.x), f1 = h22f2(w.y), f2 = h22f2(w.z), f3 = h22f2(w.w);
        w.x = f2h2(f0.x * scale, f0.y * scale);
        w.y = f2h2(f1.x * scale, f1.y * scale);
        w.z = f2h2(f2.x * scale, f2.y * scale);
        w.w = f2h2(f3.x * scale, f3.y * scale);
        *(uint4*)(sK + r * LDKV + c4) = w;
    }
    __syncthreads();

    uint32_t qf[8][4];
    #pragma unroll
    for (int ks = 0; ks < 8; ks++) {
        const int r0 = (wrow + gid) * LDKV + ks * 8;
        const int r1 = (wrow + gid + 8) * LDKV + ks * 8;
        qf[ks][0] = sK[r0 + tig];
        qf[ks][1] = sK[r1 + tig];
        qf[ks][2] = sK[r0 + tig + 4];
        qf[ks][3] = sK[r1 + tig + 4];
    }
    __syncthreads();   // frag reads done before cp.async overwrites sK

    auto load_tile = [&](int t) {
        uint32_t* dK = sK + (t % 3) * KVBUF;
        uint32_t* dV = sV + (t % 3) * KVBUF;
        const size_t row0 = (size_t)t * 64;
        #pragma unroll
        for (int ch = 0; ch < 4; ch++) {
            const int i = tid + ch * 256;
            const int r = i >> 4, c4 = (i & 15) * 4;
            CP_ASYNC16(smem_u32(dK + r * LDKV + c4), Kb + (row0 + r) * 64 + c4);
            CP_ASYNC16(smem_u32(dV + r * LDKV + c4), Vb + (row0 + r) * 64 + c4);
        }
    };

    const int nj = (q0 >> 6) + 2;
    load_tile(0); CP_COMMIT();
    if (1 < nj) load_tile(1);
    CP_COMMIT();

    float accO[16][4];
    #pragma unroll
    for (int na = 0; na < 16; na++)
        #pragma unroll
        for (int e = 0; e < 4; e++) accO[na][e] = 0.f;
    float m0 = -INFINITY, m1 = -INFINITY, l0 = 0.f, l1 = 0.f;

    for (int j = 0; j < nj; j++) {
        const int j0 = j * 64;
        const int buf = j % 3;
        CP_WAIT(1);
        __syncthreads();

        if (j + 2 < nj) load_tile(j + 2);
        CP_COMMIT();

        if (j0 > q0 + wrow + 15) continue;

        const uint32_t* K0 = sK + buf * KVBUF;
        const uint32_t sVbase = smem_u32(sV) + buf * KVBUF * 4;

        // ---- S = Q K^T ----
        float accS[8][4];
        #pragma unroll
        for (int na = 0; na < 8; na++)
            #pragma unroll
            for (int e = 0; e < 4; e++) accS[na][e] = 0.f;

        #pragma unroll
        for (int ks = 0; ks < 8; ks++) {
            #pragma unroll
            for (int na = 0; na < 8; na++) {
                const int nb = (na * 8 + gid) * LDKV + ks * 8;
                uint32_t b[2];
                b[0] = K0[nb + tig];
                b[1] = K0[nb + tig + 4];
                MMA_F16(accS[na], qf[ks], b);
            }
        }

        // ---- causal mask ----
        if (j0 + 63 > q0 + wrow) {
            const int qi0 = q0 + wrow + gid;
            const int qi1 = qi0 + 8;
            #pragma unroll
            for (int na = 0; na < 8; na++) {
                const int c0 = j0 + na * 8 + 2 * tig;
                if (c0 > qi0)     accS[na][0] = -INFINITY;
                if (c0 + 1 > qi0) accS[na][1] = -INFINITY;
                if (c0 > qi1)     accS[na][2] = -INFINITY;
                if (c0 + 1 > qi1) accS[na][3] = -INFINITY;
            }
        }

        // ---- warp-local online softmax ----
        float mt0 = -INFINITY, mt1 = -INFINITY;
        #pragma unroll
        for (int na = 0; na < 8; na++) {
            mt0 = fmaxf(mt0, fmaxf(accS[na][0], accS[na][1]));
            mt1 = fmaxf(mt1, fmaxf(accS[na][2], accS[na][3]));
        }
        mt0 = fmaxf(mt0, __shfl_xor_sync(0xffffffffu, mt0, 1));
        mt0 = fmaxf(mt0, __shfl_xor_sync(0xffffffffu, mt0, 2));
        mt1 = fmaxf(mt1, __shfl_xor_sync(0xffffffffu, mt1, 1));
        mt1 = fmaxf(mt1, __shfl_xor_sync(0xffffffffu, mt1, 2));
        const float mn0 = fmaxf(m0, mt0);
        const float mn1 = fmaxf(m1, mt1);
        const float al0 = __expf(m0 - mn0);
        const float al1 = __expf(m1 - mn1);
        m0 = mn0; m1 = mn1;
        float ls0 = 0.f, ls1 = 0.f;
        #pragma unroll
        for (int na = 0; na < 8; na++) {
            accS[na][0] = __expf(accS[na][0] - mn0);
            accS[na][1] = __expf(accS[na][1] - mn0);
            accS[na][2] = __expf(accS[na][2] - mn1);
            accS[na][3] = __expf(accS[na][3] - mn1);
            ls0 += accS[na][0] + accS[na][1];
            ls1 += accS[na][2] + accS[na][3];
        }
        ls0 += __shfl_xor_sync(0xffffffffu, ls0, 1);
        ls0 += __shfl_xor_sync(0xffffffffu, ls0, 2);
        ls1 += __shfl_xor_sync(0xffffffffu, ls1, 1);
        ls1 += __shfl_xor_sync(0xffffffffu, ls1, 2);
        l0 = l0 * al0 + ls0;
        l1 = l1 * al1 + ls1;

        // ---- rescale accO ----
        #pragma unroll
        for (int na = 0; na < 16; na++) {
            accO[na][0] *= al0; accO[na][1] *= al0;
            accO[na][2] *= al1; accO[na][3] *= al1;
        }

        // ---- O += P V : P converted in registers (C-frag == A-frag) ----
        #pragma unroll
        for (int ks = 0; ks < 4; ks++) {
            uint32_t a[4];
            a[0] = f2h2(accS[2 * ks][0],     accS[2 * ks][1]);
            a[1] = f2h2(accS[2 * ks][2],     accS[2 * ks][3]);
            a[2] = f2h2(accS[2 * ks + 1][0], accS[2 * ks + 1][1]);
            a[3] = f2h2(accS[2 * ks + 1][2], accS[2 * ks + 1][3]);
            #pragma unroll
            for (int nb = 0; nb < 8; nb++) {
                uint32_t b0, b1, b2, b3;
                const uint32_t addr = sVbase +
                    (uint32_t)(((ks * 16 + (lane & 15)) * LDKV
                                + nb * 8 + (lane >> 4) * 4) * 4);
                LDMATRIX_X4_TRANS(b0, b1, b2, b3, addr);
                uint32_t be[2] = {b0, b1};
                uint32_t bo[2] = {b2, b3};
                MMA_F16(accO[2 * nb],     a, be);
                MMA_F16(accO[2 * nb + 1], a, bo);
            }
        }
    }

    // ---- normalize + pack fp16 out, PERMUTED group order for proj GEMM ----
    const int b = bh >> 4, h = bh & 15;
    const float inv0 = 1.f / l0;
    const float inv1 = 1.f / l1;
    const int t0 = q0 + wrow + gid;
    uint32_t* base0 = O + ((size_t)(b * TT + t0)) * (NN / 2) + h * 64;
    uint32_t* base1 = O + ((size_t)(b * TT + t0 + 8)) * (NN / 2) + h * 64;
    #pragma unroll
    for (int na = 0; na < 16; na++) {
        const int lq = na * 4 + tig;   // plain local k2 index 0..63
        const int out = (lq & ~7) |
                        ((lq & 4) ? ((lq & 3) * 2 + 1) : ((lq & 3) * 2));
        base0[out] = f2h2(accO[na][0] * inv0, accO[na][1] * inv0);
        base1[out] = f2h2(accO[na][2] * inv1, accO[na][3] * inv1);
    }
}

// ---------------------------------------------------------------------------
extern "C" void kernel_launch(void* const* d_in, const int* in_sizes, int n_in,
                              void* d_out, int out_size)
{
    const float* x  = (const float*)d_in[0];
    const float* Wq = (const float*)d_in[1];
    const float* bq = (const float*)d_in[2];
    const float* Wk = (const float*)d_in[3];
    const float* bk = (const float*)d_in[4];
    const float* Wv = (const float*)d_in[5];
    const float* bv = (const float*)d_in[6];
    const float* Wp = (const float*)d_in[7];
    const float* bp = (const float*)d_in[8];
    float* out = (float*)d_out;

    uint32_t *q, *k, *v, *o, *xh, *wq, *wk, *wv, *wp;
    cudaGetSymbolAddress((void**)&q,  g_q);
    cudaGetSymbolAddress((void**)&k,  g_k);
    cudaGetSymbolAddress((void**)&v,  g_v);
    cudaGetSymbolAddress((void**)&o,  g_o);
    cudaGetSymbolAddress((void**)&xh, g_x);
    cudaGetSymbolAddress((void**)&wq, g_wq);
    cudaGetSymbolAddress((void**)&wk, g_wk);
    cudaGetSymbolAddress((void**)&wv, g_wv);
    cudaGetSymbolAddress((void**)&wp, g_wp);

    cudaFuncSetAttribute(attn_f16, cudaFuncAttributeMaxDynamicSharedMemorySize, ATTN_SMEM);
    cudaFuncSetAttribute(gemm_qkv, cudaFuncAttributeMaxDynamicSharedMemorySize, GEMM_SMEM);
    cudaFuncSetAttribute(gemm_proj, cudaFuncAttributeMaxDynamicSharedMemorySize, GEMM_SMEM);

    // Pre-passes
    const int ngroups = MM * 128;
    pack_x_perm<<<(ngroups + 255) / 256, 256>>>(x, xh, ngroups);
    pack_w_qkv<<<dim3(KK / 32, 128 / 32, 48), 256>>>(Wq, Wk, Wv, wq, wk, wv);
    pack_w_p<<<dim3(KK / 32, NN / 32), 256>>>(Wp, wp);

    gemm_qkv<<<dim3(NN / 128, MM / 128, 3), 256, GEMM_SMEM>>>(
        xh, wq, bq, wk, bk, wv, bv, q, k, v);

    attn_f16<<<dim3(TT / 128, BB * HH), 256, ATTN_SMEM>>>(q, k, v, o);

    gemm_proj<<<dim3(NN / 128, MM / 128), 256, GEMM_SMEM>>>(o, wp, bp, out);
}

// round 16
// speedup vs baseline: 1.0225x; 1.0225x over previous
#include <cuda_runtime.h>
#include <cuda_fp16.h>
#include <math.h>
#include <stdint.h>

#define BB  2
#define TT  2048
#define DD  2048
#define HH  16
#define DHH 128
#define MM  (BB*TT)    // 4096
#define NN  (HH*DHH)   // 2048
#define KK  DD         // 2048
#define K2  (KK/2)     // 1024

// Scratch (allocation-free rule: __device__ globals). All fp16x2-packed u32.
// x and qkv-weights use PERMUTED k2-groups (order 0,4,1,5,2,6,3,7 within each
// 8-word group) for LDS.64 fragment loads in gemm_qkv. qkv weights n-major.
// q/k/v, o, and wp are PLAIN layouts (attention + proj use R13 paths).
__device__ uint32_t g_q[(size_t)BB*HH*TT*(DHH/2)];
__device__ uint32_t g_k[(size_t)BB*HH*TT*(DHH/2)];
__device__ uint32_t g_v[(size_t)BB*HH*TT*(DHH/2)];
__device__ uint32_t g_o[(size_t)MM*(NN/2)];      // plain
__device__ uint32_t g_x[(size_t)MM*K2];          // permuted groups
__device__ uint32_t g_wq[(size_t)NN*K2];         // n-major, permuted groups
__device__ uint32_t g_wk[(size_t)NN*K2];
__device__ uint32_t g_wv[(size_t)NN*K2];
__device__ uint32_t g_wp[(size_t)K2*NN];         // plain k2-major [k2][n]

__device__ __forceinline__ uint32_t f2h2(float a, float b) {
    __half2 h = __floats2half2_rn(a, b);
    return *(uint32_t*)&h;
}
__device__ __forceinline__ float2 h22f2(uint32_t w) {
    return __half22float2(*(__half2*)&w);
}

#define MMA_F16(c, a, b)                                                      \
    asm volatile(                                                             \
        "mma.sync.aligned.m16n8k16.row.col.f32.f16.f16.f32 "                  \
        "{%0,%1,%2,%3}, {%4,%5,%6,%7}, {%8,%9}, {%0,%1,%2,%3};"               \
        : "+f"((c)[0]), "+f"((c)[1]), "+f"((c)[2]), "+f"((c)[3])              \
        : "r"((a)[0]), "r"((a)[1]), "r"((a)[2]), "r"((a)[3]),                 \
          "r"((b)[0]), "r"((b)[1]))

#define LDMATRIX_X4_TRANS(r0, r1, r2, r3, addr)                               \
    asm volatile(                                                             \
        "ldmatrix.sync.aligned.m8n8.x4.trans.shared.b16 {%0,%1,%2,%3}, [%4];" \
        : "=r"(r0), "=r"(r1), "=r"(r2), "=r"(r3) : "r"(addr))

__device__ __forceinline__ uint32_t smem_u32(const void* p) {
    return (uint32_t)__cvta_generic_to_shared(p);
}
#define CP_ASYNC16(dst_u32, src)                                              \
    asm volatile("cp.async.cg.shared.global [%0], [%1], 16;"                  \
                 :: "r"(dst_u32), "l"(src))
#define CP_COMMIT() asm volatile("cp.async.commit_group;")
#define CP_WAIT(n)  asm volatile("cp.async.wait_group %0;" :: "n"(n))

// ---------------------------------------------------------------------------
// Pre-pass 1: pack x fp32 -> fp16x2, permuted k2-groups. One thread per group.
// ---------------------------------------------------------------------------
__global__ __launch_bounds__(256) void pack_x_perm(
    const float* __restrict__ src, uint32_t* __restrict__ dst, int ngroups)
{
    const int i = blockIdx.x * 256 + threadIdx.x;
    if (i >= ngroups) return;
    const int row = i >> 7, grp = i & 127;
    const float* s = src + (size_t)row * KK + grp * 16;
    float f[16];
    #pragma unroll
    for (int j = 0; j < 4; j++) {
        float4 v = ((const float4*)s)[j];
        f[4 * j] = v.x; f[4 * j + 1] = v.y; f[4 * j + 2] = v.z; f[4 * j + 3] = v.w;
    }
    uint32_t o[8];
    #pragma unroll
    for (int p = 0; p < 8; p++) {
        const int q = (p & 1) ? (p >> 1) + 4 : (p >> 1);
        o[p] = f2h2(f[2 * q], f[2 * q + 1]);
    }
    uint32_t* d = dst + (size_t)row * K2 + grp * 8;
    ((uint4*)d)[0] = make_uint4(o[0], o[1], o[2], o[3]);
    ((uint4*)d)[1] = make_uint4(o[4], o[5], o[6], o[7]);
}

// ---------------------------------------------------------------------------
// Pre-pass 2a: qkv weights -> n-major [n][K2], permuted groups (smem tile).
// ---------------------------------------------------------------------------
__device__ __forceinline__ void pack_tile_perm(
    const float* __restrict__ src, uint32_t* __restrict__ dst,
    int ld, int k0, int n0, int tid)
{
    __shared__ float t[32][33];
    const int tx = tid & 31, ty = tid >> 5;
    #pragma unroll
    for (int i = 0; i < 32; i += 8)
        t[ty + i][tx] = src[(size_t)(k0 + ty + i) * ld + n0 + tx];
    __syncthreads();
    const int r = tid >> 3;
    const int c = (tid & 7) * 2;
    #pragma unroll
    for (int e = 0; e < 2; e++) {
        const int q = c + e;
        const int pp = (q & 4) ? ((q & 3) * 2 + 1) : ((q & 3) * 2);
        const int outk2 = (k0 >> 1) + (q >> 3) * 8 + pp;
        dst[(size_t)(n0 + r) * K2 + outk2] = f2h2(t[2 * q][r], t[2 * q + 1][r]);
    }
}

__global__ __launch_bounds__(256) void pack_w_qkv(
    const float* __restrict__ Wq, const float* __restrict__ Wk,
    const float* __restrict__ Wv,
    uint32_t* __restrict__ dq, uint32_t* __restrict__ dk,
    uint32_t* __restrict__ dv)
{
    const int z = blockIdx.z, which = z >> 4, h = z & 15;
    const float* src = ((which == 0) ? Wq : (which == 1) ? Wk : Wv)
                       + (size_t)h * KK * 128;
    uint32_t* dst = ((which == 0) ? dq : (which == 1) ? dk : dv)
                    + (size_t)h * 128 * K2;
    pack_tile_perm(src, dst, 128, blockIdx.x * 32, blockIdx.y * 32, threadIdx.x);
}

// Pre-pass 2b: proj weight plain pack: [K][NN] -> [K2][NN] (R13 style)
__global__ __launch_bounds__(256) void pack_w_p(
    const float* __restrict__ src, uint32_t* __restrict__ dst)
{
    const int idx = blockIdx.x * 256 + threadIdx.x;
    const int k2 = idx >> 9;
    const int nq = idx & 511;
    if (k2 >= K2) return;
    float4 r0 = *(const float4*)(src + (size_t)(2 * k2) * NN + nq * 4);
    float4 r1 = *(const float4*)(src + (size_t)(2 * k2 + 1) * NN + nq * 4);
    uint4 o;
    o.x = f2h2(r0.x, r1.x);
    o.y = f2h2(r0.y, r1.y);
    o.z = f2h2(r0.z, r1.z);
    o.w = f2h2(r0.w, r1.w);
    *(uint4*)(dst + (size_t)k2 * NN + nq * 4) = o;
}

// ========================= gemm_qkv (R15 winner) ===========================
// BM=BN=128, K-chunk=16 (8 u32), 3 stages, 8 warps 2x4, wt 64x32,
// permuted-group LDS.64 fragment loads. Plain headed fp16 output.
#define LDG 8
#define STG (128 * LDG)
#define GEMM_SMEM_QKV (6 * STG * 4)        // 24576 bytes

__global__ __launch_bounds__(256, 2) void gemm_qkv(
    const uint32_t* __restrict__ A,
    const uint32_t* __restrict__ Wq, const float* __restrict__ bq,
    const uint32_t* __restrict__ Wk, const float* __restrict__ bk,
    const uint32_t* __restrict__ Wv, const float* __restrict__ bv,
    uint32_t* __restrict__ Cq, uint32_t* __restrict__ Ck, uint32_t* __restrict__ Cv)
{
    extern __shared__ uint32_t smu[];
    uint32_t* As = smu;                 // [3][128][8]
    uint32_t* Bs = smu + 3 * STG;       // [3][128][8]

    const int bx = blockIdx.x, by = blockIdx.y, bz = blockIdx.z;
    const int tid = threadIdx.x;
    const int wid = tid >> 5, lane = tid & 31;
    const int gid = lane >> 2, tig = lane & 3;
    const int wr = wid >> 2, wc = wid & 3;
    const int m0 = by * 128;

    const uint32_t* W  = (bz == 0) ? Wq : (bz == 1) ? Wk : Wv;
    const float* bias  = (bz == 0) ? bq : (bz == 1) ? bk : bv;
    uint32_t* C        = (bz == 0) ? Cq : (bz == 1) ? Ck : Cv;

    const int srow = tid >> 1, skoff = (tid & 1) * 4;
    const uint32_t* Asrc = A + (size_t)(m0 + srow) * K2 + skoff;
    const uint32_t* Bsrc = W + (size_t)(bx * 128 + srow) * K2 + skoff;
    const uint32_t soff = (srow * LDG + skoff) * 4;

    auto load_stage = [&](int s, int k2b) {
        CP_ASYNC16(smem_u32(As) + s * STG * 4 + soff, Asrc + k2b);
        CP_ASYNC16(smem_u32(Bs) + s * STG * 4 + soff, Bsrc + k2b);
    };

    float acc[4][4][4];
    #pragma unroll
    for (int i = 0; i < 4; i++)
        #pragma unroll
        for (int j = 0; j < 4; j++)
            #pragma unroll
            for (int e = 0; e < 4; e++) acc[i][j][e] = 0.f;

    load_stage(0, 0); CP_COMMIT();
    load_stage(1, 8); CP_COMMIT();

    int cur = 0, nxt = 2, knext = 16;
    for (int it = 0; it < 128; it++) {
        CP_WAIT(1);
        __syncthreads();

        const uint32_t* Ac = As + cur * STG;
        const uint32_t* Bc = Bs + cur * STG;

        uint32_t af[4][4], bf[4][2];
        #pragma unroll
        for (int ma = 0; ma < 4; ma++) {
            const uint32_t* p0 = Ac + (wr * 64 + ma * 16 + gid) * LDG + 2 * tig;
            uint2 lo = *(const uint2*)p0;
            uint2 hi = *(const uint2*)(p0 + 8 * LDG);
            af[ma][0] = lo.x; af[ma][2] = lo.y;
            af[ma][1] = hi.x; af[ma][3] = hi.y;
        }
        #pragma unroll
        for (int na = 0; na < 4; na++) {
            uint2 b = *(const uint2*)(Bc + (wc * 32 + na * 8 + gid) * LDG + 2 * tig);
            bf[na][0] = b.x; bf[na][1] = b.y;
        }
        #pragma unroll
        for (int ma = 0; ma < 4; ma++)
            #pragma unroll
            for (int na = 0; na < 4; na++)
                MMA_F16(acc[ma][na], af[ma], bf[na]);

        if (knext < K2) load_stage(nxt, knext);
        CP_COMMIT();
        knext += 8;
        cur = (cur == 2) ? 0 : cur + 1;
        nxt = (nxt == 2) ? 0 : nxt + 1;
    }

    // Epilogue: bias + pack fp16, plain headed layout [B,H,T,Dh/2]
    #pragma unroll
    for (int ma = 0; ma < 4; ma++) {
        #pragma unroll
        for (int na = 0; na < 4; na++) {
            const int r   = m0 + wr * 64 + ma * 16 + gid;
            const int nl  = wc * 32 + na * 8 + 2 * tig;
            const int ng  = bx * 128 + nl;
            const float b0 = bias[ng], b1 = bias[ng + 1];
            const int col2 = nl >> 1;
            const int bb0 = r >> 11,       t0 = r & (TT - 1);
            const int bb1 = (r + 8) >> 11, t1 = (r + 8) & (TT - 1);
            C[(((size_t)(bb0 * HH + bx)) * TT + t0) * 64 + col2] =
                f2h2(acc[ma][na][0] + b0, acc[ma][na][1] + b1);
            C[(((size_t)(bb1 * HH + bx)) * TT + t1) * 64 + col2] =
                f2h2(acc[ma][na][2] + b0, acc[ma][na][3] + b1);
        }
    }
}

// ======================== gemm_proj (R13 config) ===========================
#define LDA2 12
#define LDB2 136
#define A_STG (128 * LDA2)
#define B_STG (8 * LDB2)
#define GEMM_SMEM_P (3 * (A_STG + B_STG) * 4)   // 31488 bytes

__global__ __launch_bounds__(256, 2) void gemm_proj(
    const uint32_t* __restrict__ A, const uint32_t* __restrict__ W,
    const float* __restrict__ bias, float* __restrict__ C)
{
    extern __shared__ uint32_t smu[];
    uint32_t* As = smu;
    uint32_t* Bs = smu + 3 * A_STG;

    const int bx = blockIdx.x, by = blockIdx.y, tid = threadIdx.x;
    const int wid = tid >> 5, lane = tid & 31;
    const int gid = lane >> 2, tig = lane & 3;
    const int wr = wid >> 2, wc = wid & 3;
    const int m0 = by * 128;

    const uint32_t* Asrc = A + (size_t)(m0 + (tid >> 1)) * K2 + (tid & 1) * 4;
    const uint32_t* Bsrc = W + (size_t)(tid >> 5) * NN + bx * 128 + (tid & 31) * 4;

    const uint32_t aoff = ((tid >> 1) * LDA2 + (tid & 1) * 4);
    const uint32_t boff = ((tid >> 5) * LDB2 + (tid & 31) * 4);

    auto load_stage = [&](int s, int k2b) {
        CP_ASYNC16(smem_u32(As + s * A_STG + aoff), Asrc + k2b);
        CP_ASYNC16(smem_u32(Bs + s * B_STG + boff), Bsrc + (size_t)k2b * NN);
    };

    float acc[4][4][4];
    #pragma unroll
    for (int i = 0; i < 4; i++)
        #pragma unroll
        for (int j = 0; j < 4; j++)
            #pragma unroll
            for (int e = 0; e < 4; e++) acc[i][j][e] = 0.f;

    load_stage(0, 0); CP_COMMIT();
    load_stage(1, 8); CP_COMMIT();

    int cur = 0, nxt = 2, knext = 16;
    for (int it = 0; it < 128; it++) {
        CP_WAIT(1);
        __syncthreads();

        const uint32_t* Ac = As + cur * A_STG;
        const uint32_t* Bc = Bs + cur * B_STG;

        uint32_t af[4][4], bf[4][2];
        #pragma unroll
        for (int ma = 0; ma < 4; ma++) {
            const int r = (wr * 64 + ma * 16 + gid) * LDA2;
            af[ma][0] = Ac[r + tig];
            af[ma][1] = Ac[r + 8 * LDA2 + tig];
            af[ma][2] = Ac[r + tig + 4];
            af[ma][3] = Ac[r + 8 * LDA2 + tig + 4];
        }
        #pragma unroll
        for (int na = 0; na < 4; na++) {
            const int n = wc * 32 + na * 8 + gid;
            bf[na][0] = Bc[tig * LDB2 + n];
            bf[na][1] = Bc[(tig + 4) * LDB2 + n];
        }
        #pragma unroll
        for (int ma = 0; ma < 4; ma++)
            #pragma unroll
            for (int na = 0; na < 4; na++)
                MMA_F16(acc[ma][na], af[ma], bf[na]);

        if (knext < K2) load_stage(nxt, knext);
        CP_COMMIT();
        knext += 8;
        cur = (cur == 2) ? 0 : cur + 1;
        nxt = (nxt == 2) ? 0 : nxt + 1;
    }

    #pragma unroll
    for (int ma = 0; ma < 4; ma++) {
        #pragma unroll
        for (int na = 0; na < 4; na++) {
            const int r  = m0 + wr * 64 + ma * 16 + gid;
            const int nl = wc * 32 + na * 8 + 2 * tig;
            const int ng = bx * 128 + nl;
            const float b0 = bias[ng], b1 = bias[ng + 1];
            float2 v0, v1;
            v0.x = acc[ma][na][0] + b0; v0.y = acc[ma][na][1] + b1;
            v1.x = acc[ma][na][2] + b0; v1.y = acc[ma][na][3] + b1;
            *(float2*)(C + (size_t)r * NN + ng) = v0;
            *(float2*)(C + (size_t)(r + 8) * NN + ng) = v1;
        }
    }
}

// ===================== attention (R13 config, 655.5) =======================
#define LDKV 68
#define LDP2 36
#define KVBUF (64 * LDKV)
#define ATTN_SMEM ((4 * KVBUF + 128 * LDP2) * 4)   // 88064 bytes

__global__ __launch_bounds__(256) void attn_f16(
    const uint32_t* __restrict__ Q, const uint32_t* __restrict__ Kg,
    const uint32_t* __restrict__ Vg, uint32_t* __restrict__ O)
{
    extern __shared__ uint32_t shu[];
    uint32_t* sK = shu;                // [2][64][68]; Q staging [128][68]
    uint32_t* sV = shu + 2 * KVBUF;    // [2][64][68]
    uint32_t* sP = shu + 4 * KVBUF;    // [128][36]

    const int bh = blockIdx.y;
    const int q0 = (int)(gridDim.x - 1 - blockIdx.x) * 128;   // big-first
    const int tid = threadIdx.x, wid = tid >> 5, lane = tid & 31;
    const int gid = lane >> 2, tig = lane & 3;
    const int wrow = wid * 16;
    const float scale = 0.08838834764831845f;   // 1/sqrt(128)

    const uint32_t* Qb = Q  + (size_t)bh * TT * 64;
    const uint32_t* Kb = Kg + (size_t)bh * TT * 64;
    const uint32_t* Vb = Vg + (size_t)bh * TT * 64;

    // ---- Stage Q (scale + fp16 re-round) into sK region ----
    #pragma unroll
    for (int ch = 0; ch < 8; ch++) {
        const int i = tid + ch * 256;
        const int r = i >> 4, c4 = (i & 15) * 4;
        uint4 w = *(const uint4*)(Qb + (size_t)(q0 + r) * 64 + c4);
        float2 f0 = h22f2(w.x), f1 = h22f2(w.y), f2 = h22f2(w.z), f3 = h22f2(w.w);
        w.x = f2h2(f0.x * scale, f0.y * scale);
        w.y = f2h2(f1.x * scale, f1.y * scale);
        w.z = f2h2(f2.x * scale, f2.y * scale);
        w.w = f2h2(f3.x * scale, f3.y * scale);
        *(uint4*)(sK + r * LDKV + c4) = w;
    }
    __syncthreads();

    uint32_t qf[8][4];
    #pragma unroll
    for (int ks = 0; ks < 8; ks++) {
        const int r0 = (wrow + gid) * LDKV + ks * 8;
        const int r1 = (wrow + gid + 8) * LDKV + ks * 8;
        qf[ks][0] = sK[r0 + tig];
        qf[ks][1] = sK[r1 + tig];
        qf[ks][2] = sK[r0 + tig + 4];
        qf[ks][3] = sK[r1 + tig + 4];
    }
    __syncthreads();

    #pragma unroll
    for (int ch = 0; ch < 4; ch++) {
        const int i = tid + ch * 256;
        const int r = i >> 4, c4 = (i & 15) * 4;
        CP_ASYNC16(smem_u32(sK + r * LDKV + c4), Kb + (size_t)r * 64 + c4);
        CP_ASYNC16(smem_u32(sV + r * LDKV + c4), Vb + (size_t)r * 64 + c4);
    }
    CP_COMMIT();

    float accO[16][4];
    #pragma unroll
    for (int na = 0; na < 16; na++)
        #pragma unroll
        for (int e = 0; e < 4; e++) accO[na][e] = 0.f;
    float m0 = -INFINITY, m1 = -INFINITY, l0 = 0.f, l1 = 0.f;

    const int nj = (q0 >> 6) + 2;
    for (int j = 0; j < nj; j++) {
        const int j0 = j * 64;
        const int buf = j & 1;
        CP_WAIT(0);
        __syncthreads();

        if (j + 1 < nj) {
            uint32_t* dK = sK + (buf ^ 1) * KVBUF;
            uint32_t* dV = sV + (buf ^ 1) * KVBUF;
            const size_t row0 = (size_t)(j0 + 64);
            #pragma unroll
            for (int ch = 0; ch < 4; ch++) {
                const int i = tid + ch * 256;
                const int r = i >> 4, c4 = (i & 15) * 4;
                CP_ASYNC16(smem_u32(dK + r * LDKV + c4),
                           Kb + (row0 + r) * 64 + c4);
                CP_ASYNC16(smem_u32(dV + r * LDKV + c4),
                           Vb + (row0 + r) * 64 + c4);
            }
            CP_COMMIT();
        }

        if (j0 > q0 + wrow + 15) continue;

        const uint32_t* K0 = sK + buf * KVBUF;
        const uint32_t sVbase = smem_u32(sV) + buf * KVBUF * 4;

        // ---- S = Q K^T ----
        float accS[8][4];
        #pragma unroll
        for (int na = 0; na < 8; na++)
            #pragma unroll
            for (int e = 0; e < 4; e++) accS[na][e] = 0.f;

        #pragma unroll
        for (int ks = 0; ks < 8; ks++) {
            #pragma unroll
            for (int na = 0; na < 8; na++) {
                const int nb = (na * 8 + gid) * LDKV + ks * 8;
                uint32_t b[2];
                b[0] = K0[nb + tig];
                b[1] = K0[nb + tig + 4];
                MMA_F16(accS[na], qf[ks], b);
            }
        }

        // ---- causal mask ----
        if (j0 + 63 > q0 + wrow) {
            const int qi0 = q0 + wrow + gid;
            const int qi1 = qi0 + 8;
            #pragma unroll
            for (int na = 0; na < 8; na++) {
                const int c0 = j0 + na * 8 + 2 * tig;
                if (c0 > qi0)     accS[na][0] = -INFINITY;
                if (c0 + 1 > qi0) accS[na][1] = -INFINITY;
                if (c0 > qi1)     accS[na][2] = -INFINITY;
                if (c0 + 1 > qi1) accS[na][3] = -INFINITY;
            }
        }

        // ---- warp-local online softmax ----
        float mt0 = -INFINITY, mt1 = -INFINITY;
        #pragma unroll
        for (int na = 0; na < 8; na++) {
            mt0 = fmaxf(mt0, fmaxf(accS[na][0], accS[na][1]));
            mt1 = fmaxf(mt1, fmaxf(accS[na][2], accS[na][3]));
        }
        mt0 = fmaxf(mt0, __shfl_xor_sync(0xffffffffu, mt0, 1));
        mt0 = fmaxf(mt0, __shfl_xor_sync(0xffffffffu, mt0, 2));
        mt1 = fmaxf(mt1, __shfl_xor_sync(0xffffffffu, mt1, 1));
        mt1 = fmaxf(mt1, __shfl_xor_sync(0xffffffffu, mt1, 2));
        const float mn0 = fmaxf(m0, mt0);
        const float mn1 = fmaxf(m1, mt1);
        const float al0 = __expf(m0 - mn0);
        const float al1 = __expf(m1 - mn1);
        m0 = mn0; m1 = mn1;
        float ls0 = 0.f, ls1 = 0.f;
        #pragma unroll
        for (int na = 0; na < 8; na++) {
            accS[na][0] = __expf(accS[na][0] - mn0);
            accS[na][1] = __expf(accS[na][1] - mn0);
            accS[na][2] = __expf(accS[na][2] - mn1);
            accS[na][3] = __expf(accS[na][3] - mn1);
            ls0 += accS[na][0] + accS[na][1];
            ls1 += accS[na][2] + accS[na][3];
        }
        ls0 += __shfl_xor_sync(0xffffffffu, ls0, 1);
        ls0 += __shfl_xor_sync(0xffffffffu, ls0, 2);
        ls1 += __shfl_xor_sync(0xffffffffu, ls1, 1);
        ls1 += __shfl_xor_sync(0xffffffffu, ls1, 2);
        l0 = l0 * al0 + ls0;
        l1 = l1 * al1 + ls1;

        // ---- P -> warp-private smem rows, fp16-packed ----
        #pragma unroll
        for (int na = 0; na < 8; na++) {
            const int c2 = na * 4 + tig;
            sP[(wrow + gid) * LDP2 + c2]     = f2h2(accS[na][0], accS[na][1]);
            sP[(wrow + gid + 8) * LDP2 + c2] = f2h2(accS[na][2], accS[na][3]);
        }
        __syncwarp();

        #pragma unroll
        for (int na = 0; na < 16; na++) {
            accO[na][0] *= al0; accO[na][1] *= al0;
            accO[na][2] *= al1; accO[na][3] *= al1;
        }

        // ---- O += P V  (V frags via ldmatrix.trans) ----
        #pragma unroll
        for (int ks = 0; ks < 4; ks++) {
            uint32_t a[4];
            const int r0 = (wrow + gid) * LDP2 + ks * 8;
            const int r1 = (wrow + gid + 8) * LDP2 + ks * 8;
            a[0] = sP[r0 + tig];
            a[1] = sP[r1 + tig];
            a[2] = sP[r0 + tig + 4];
            a[3] = sP[r1 + tig + 4];
            #pragma unroll
            for (int nb = 0; nb < 8; nb++) {
                uint32_t b0, b1, b2, b3;
                const uint32_t addr = sVbase +
                    (uint32_t)(((ks * 16 + (lane & 15)) * LDKV
                                + nb * 8 + (lane >> 4) * 4) * 4);
                LDMATRIX_X4_TRANS(b0, b1, b2, b3, addr);
                uint32_t be[2] = {b0, b1};
                uint32_t bo[2] = {b2, b3};
                MMA_F16(accO[2 * nb],     a, be);
                MMA_F16(accO[2 * nb + 1], a, bo);
            }
        }
    }

    // ---- normalize + pack fp16 out [M][NN/2] u32 (plain, coalesced) ----
    const int b = bh >> 4, h = bh & 15;
    const float inv0 = 1.f / l0;
    const float inv1 = 1.f / l1;
    const int t0 = q0 + wrow + gid;
    uint32_t* base0 = O + ((size_t)(b * TT + t0)) * (NN / 2) + h * 64;
    uint32_t* base1 = O + ((size_t)(b * TT + t0 + 8)) * (NN / 2) + h * 64;
    #pragma unroll
    for (int na = 0; na < 16; na++) {
        const int c2 = na * 4 + tig;
        base0[c2] = f2h2(accO[na][0] * inv0, accO[na][1] * inv0);
        base1[c2] = f2h2(accO[na][2] * inv1, accO[na][3] * inv1);
    }
}

// ---------------------------------------------------------------------------
extern "C" void kernel_launch(void* const* d_in, const int* in_sizes, int n_in,
                              void* d_out, int out_size)
{
    const float* x  = (const float*)d_in[0];
    const float* Wq = (const float*)d_in[1];
    const float* bq = (const float*)d_in[2];
    const float* Wk = (const float*)d_in[3];
    const float* bk = (const float*)d_in[4];
    const float* Wv = (const float*)d_in[5];
    const float* bv = (const float*)d_in[6];
    const float* Wp = (const float*)d_in[7];
    const float* bp = (const float*)d_in[8];
    float* out = (float*)d_out;

    uint32_t *q, *k, *v, *o, *xh, *wq, *wk, *wv, *wp;
    cudaGetSymbolAddress((void**)&q,  g_q);
    cudaGetSymbolAddress((void**)&k,  g_k);
    cudaGetSymbolAddress((void**)&v,  g_v);
    cudaGetSymbolAddress((void**)&o,  g_o);
    cudaGetSymbolAddress((void**)&xh, g_x);
    cudaGetSymbolAddress((void**)&wq, g_wq);
    cudaGetSymbolAddress((void**)&wk, g_wk);
    cudaGetSymbolAddress((void**)&wv, g_wv);
    cudaGetSymbolAddress((void**)&wp, g_wp);

    cudaFuncSetAttribute(attn_f16, cudaFuncAttributeMaxDynamicSharedMemorySize, ATTN_SMEM);
    cudaFuncSetAttribute(gemm_qkv, cudaFuncAttributeMaxDynamicSharedMemorySize, GEMM_SMEM_QKV);
    cudaFuncSetAttribute(gemm_proj, cudaFuncAttributeMaxDynamicSharedMemorySize, GEMM_SMEM_P);

    // Pre-passes
    const int ngroups = MM * 128;
    pack_x_perm<<<(ngroups + 255) / 256, 256>>>(x, xh, ngroups);
    pack_w_qkv<<<dim3(KK / 32, 128 / 32, 48), 256>>>(Wq, Wk, Wv, wq, wk, wv);
    pack_w_p<<<(K2 * 512 + 255) / 256, 256>>>(Wp, wp);

    gemm_qkv<<<dim3(NN / 128, MM / 128, 3), 256, GEMM_SMEM_QKV>>>(
        xh, wq, bq, wk, bk, wv, bv, q, k, v);

    attn_f16<<<dim3(TT / 128, BB * HH), 256, ATTN_SMEM>>>(q, k, v, o);

    gemm_proj<<<dim3(NN / 128, MM / 128), 256, GEMM_SMEM_P>>>(o, wp, bp, out);
}